// round 14
// baseline (speedup 1.0000x reference)
#include <cuda_runtime.h>
#include <cuda_bf16.h>
#include <cstdint>

#define N_NODES 50000
#define N_PAD   50176   // 392 * 128
#define N_EDGES 800000
#define DIN 128
#define DH  256
#define DOUT 64
#define NB_SCAN 49

// ---------------- scratch ------------------------------------------------------
__device__ __align__(16) float g_inv [N_NODES];
__device__ __align__(16) float g_P   [N_NODES * 2*DOUT];
__device__ __align__(16) __nv_bfloat16 g_a1h[N_PAD * DIN];
__device__ __align__(16) __nv_bfloat16 g_a1l[N_PAD * DIN];
__device__ __align__(16) __nv_bfloat16 g_xh [N_PAD * DIN];
__device__ __align__(16) __nv_bfloat16 g_xl [N_PAD * DIN];
__device__ __align__(16) __nv_bfloat16 g_hh [N_PAD * DH];
__device__ __align__(16) __nv_bfloat16 g_hl [N_PAD * DH];
__device__ __align__(16) __nv_bfloat16 g_w1h[512 * DIN];  // 0..255 W1l, 256..511 W1r
__device__ __align__(16) __nv_bfloat16 g_w1l[512 * DIN];
__device__ __align__(16) __nv_bfloat16 g_w2h[128 * DH];   // 0..63 W2l, 64..127 W2r
__device__ __align__(16) __nv_bfloat16 g_w2l[128 * DH];
__device__ int g_rowptr[N_NODES + 1];
__device__ int g_cnt   [N_NODES];
__device__ int g_col   [N_EDGES];
__device__ int g_bsum  [64];
__device__ int g_is64;

static __device__ __forceinline__ uint32_t pack_bf16x2(__nv_bfloat16 a, __nv_bfloat16 b) {
    return (uint32_t)__bfloat16_as_ushort(a) | ((uint32_t)__bfloat16_as_ushort(b) << 16);
}
static __device__ __forceinline__ void split2(float v, __nv_bfloat16& h, __nv_bfloat16& l) {
    h = __float2bfloat16(v);
    l = __float2bfloat16(v - __bfloat162float(h));
}
// unpack bf16x2 word -> two fp32 (bit ops: lo = w<<16, hi = w & 0xFFFF0000)
static __device__ __forceinline__ void unpack2f(uint32_t w, float& f0, float& f1) {
    f0 = __uint_as_float(w << 16);
    f1 = __uint_as_float(w & 0xFFFF0000u);
}

// ---------------- prep: split_x + split_w + zero counts + detect (fused) -------
__global__ void prep_kernel(const float* __restrict__ x,
                            const float* __restrict__ W1l, const float* __restrict__ W1r,
                            const float* __restrict__ W2l, const float* __restrict__ W2r,
                            const unsigned int* __restrict__ ei_words) {
    const int NX = N_NODES * (DIN / 4);   // 1,600,000 float4 units
    const int T1 = 512 * DIN;             // 65536
    const int T2 = 128 * DH;              // 32768
    int idx = blockIdx.x * blockDim.x + threadIdx.x;
    if (idx < NX) {
        float4 v = ((const float4*)x)[idx];
        __nv_bfloat16 h0, l0, h1, l1, h2, l2, h3, l3;
        split2(v.x, h0, l0); split2(v.y, h1, l1);
        split2(v.z, h2, l2); split2(v.w, h3, l3);
        *(uint2*)&g_xh[idx * 4] = make_uint2(pack_bf16x2(h0, h1), pack_bf16x2(h2, h3));
        *(uint2*)&g_xl[idx * 4] = make_uint2(pack_bf16x2(l0, l1), pack_bf16x2(l2, l3));
    } else if (idx < NX + T1) {
        int j = idx - NX;
        int row = j >> 7, col = j & 127;
        float v = (row < 256) ? W1l[row * DIN + col] : W1r[(row - 256) * DIN + col];
        __nv_bfloat16 h, l; split2(v, h, l);
        g_w1h[j] = h; g_w1l[j] = l;
    } else if (idx < NX + T1 + T2) {
        int j = idx - NX - T1;
        int row = j >> 8, col = j & 255;
        float v = (row < DOUT) ? W2l[row * DH + col] : W2r[(row - DOUT) * DH + col];
        __nv_bfloat16 h, l; split2(v, h, l);
        g_w2h[j] = h; g_w2l[j] = l;
    } else if (idx < NX + T1 + T2 + N_NODES) {
        g_cnt[idx - NX - T1 - T2] = 0;
    }
    if (idx == 0) {
        int is64 = 1;
        for (int k = 0; k < 128; ++k)
            if (ei_words[2 * k + 1] != 0u) { is64 = 0; break; }
        g_is64 = is64;
    }
}
__device__ __forceinline__ long long edge_val(const void* ei, long long idx) {
    if (g_is64) return ((const long long*)ei)[idx];
    return (long long)((const int*)ei)[idx];
}

// 4 edges per thread, wide loads
__global__ void count_kernel(const void* __restrict__ ei) {
    int t = blockIdx.x * blockDim.x + threadIdx.x;
    int e0 = t * 4;
    if (e0 >= N_EDGES) return;
    long long d[4];
    if (g_is64) {
        const longlong2* p = (const longlong2*)((const long long*)ei + N_EDGES + e0);
        longlong2 a = p[0], b = p[1];
        d[0] = a.x; d[1] = a.y; d[2] = b.x; d[3] = b.y;
    } else {
        int4 a = *(const int4*)((const int*)ei + N_EDGES + e0);
        d[0] = a.x; d[1] = a.y; d[2] = a.z; d[3] = a.w;
    }
#pragma unroll
    for (int k = 0; k < 4; ++k)
        if ((unsigned long long)d[k] < N_NODES) atomicAdd(&g_cnt[(int)d[k]], 1);
}
__global__ void blocksum_kernel() {
    int b = blockIdx.x, t = threadIdx.x;
    int i0 = b * 1024 + t * 4;
    int s = 0;
#pragma unroll
    for (int k = 0; k < 4; ++k) { int i = i0 + k; if (i < N_NODES) s += g_cnt[i]; }
    for (int off = 16; off > 0; off >>= 1) s += __shfl_down_sync(0xffffffffu, s, off);
    __shared__ int ws[8];
    int lane = t & 31, w = t >> 5;
    if (lane == 0) ws[w] = s;
    __syncthreads();
    if (t == 0) { int tot = 0; for (int k = 0; k < 8; ++k) tot += ws[k]; g_bsum[b] = tot; }
}
__global__ void rowptr_kernel() {
    __shared__ int warp_tot[8];
    __shared__ int warp_off[8];
    __shared__ int s_boff;
    int b = blockIdx.x, t = threadIdx.x;
    int lane = t & 31, w = t >> 5;
    int i0 = b * 1024 + t * 4;
    int c[4];
#pragma unroll
    for (int k = 0; k < 4; ++k) { int i = i0 + k; c[k] = (i < N_NODES) ? g_cnt[i] : 0; }
    int s = c[0] + c[1] + c[2] + c[3];
    int pre = s;
    for (int off = 1; off < 32; off <<= 1) {
        int n = __shfl_up_sync(0xffffffffu, pre, off);
        if (lane >= off) pre += n;
    }
    if (lane == 31) warp_tot[w] = pre;
    if (t == 0) {
        int off = 0;
        for (int k = 0; k < b; ++k) off += g_bsum[k];
        s_boff = off;
    }
    __syncthreads();
    if (w == 0) {
        int v = (lane < 8) ? warp_tot[lane] : 0;
        int orig = v;
        for (int off = 1; off < 8; off <<= 1) {
            int n = __shfl_up_sync(0xffffffffu, v, off);
            if (lane >= off) v += n;
        }
        if (lane < 8) warp_off[lane] = v - orig;
    }
    __syncthreads();
    int r = s_boff + warp_off[w] + (pre - s);
#pragma unroll
    for (int k = 0; k < 4; ++k) {
        int i = i0 + k;
        if (i < N_NODES) {
            g_rowptr[i] = r;
            g_cnt[i]    = r;
            g_inv[i]    = 1.0f / (float)(c[k] > 0 ? c[k] : 1);
            r += c[k];
            if (i == N_NODES - 1) g_rowptr[N_NODES] = r;
        }
    }
}
__global__ void fill_kernel(const void* __restrict__ ei) {
    int t = blockIdx.x * blockDim.x + threadIdx.x;
    int e0 = t * 2;
    if (e0 >= N_EDGES) return;
    long long s0, s1, d0, d1;
    if (g_is64) {
        longlong2 sp = *(const longlong2*)((const long long*)ei + e0);
        longlong2 dp = *(const longlong2*)((const long long*)ei + N_EDGES + e0);
        s0 = sp.x; s1 = sp.y; d0 = dp.x; d1 = dp.y;
    } else {
        int2 sp = *(const int2*)((const int*)ei + e0);
        int2 dp = *(const int2*)((const int*)ei + N_EDGES + e0);
        s0 = sp.x; s1 = sp.y; d0 = dp.x; d1 = dp.y;
    }
    if ((unsigned long long)s0 < N_NODES && (unsigned long long)d0 < N_NODES) {
        int pos = atomicAdd(&g_cnt[(int)d0], 1);
        g_col[pos] = (int)s0;
    }
    if ((unsigned long long)s1 < N_NODES && (unsigned long long)d1 < N_NODES) {
        int pos = atomicAdd(&g_cnt[(int)d1], 1);
        g_col[pos] = (int)s1;
    }
}

// ---- layer-1 aggregation: gather bf16 hi/lo of x (half the L2 bytes) ----------
// warp per node; lane handles 4 cols via one uint2 from g_xh + one from g_xl.
__global__ void __launch_bounds__(256)
agg1_kernel() {
    int w    = (blockIdx.x * blockDim.x + threadIdx.x) >> 5;
    int lane = threadIdx.x & 31;
    if (w >= N_NODES) return;
    int start = g_rowptr[w], end = g_rowptr[w + 1];
    const uint2* xh = (const uint2*)g_xh;   // row stride 32 uint2
    const uint2* xl = (const uint2*)g_xl;
    float a0 = 0.f, a1 = 0.f, a2 = 0.f, a3 = 0.f;
    int p = start;
    for (; p + 2 <= end; p += 2) {
        int s0 = g_col[p], s1 = g_col[p + 1];
        uint2 h0 = xh[(long long)s0 * 32 + lane];
        uint2 l0 = xl[(long long)s0 * 32 + lane];
        uint2 h1 = xh[(long long)s1 * 32 + lane];
        uint2 l1 = xl[(long long)s1 * 32 + lane];
        float f0, f1, f2, f3, g0, g1, g2, g3;
        unpack2f(h0.x, f0, f1); unpack2f(h0.y, f2, f3);
        unpack2f(l0.x, g0, g1); unpack2f(l0.y, g2, g3);
        a0 += f0 + g0; a1 += f1 + g1; a2 += f2 + g2; a3 += f3 + g3;
        unpack2f(h1.x, f0, f1); unpack2f(h1.y, f2, f3);
        unpack2f(l1.x, g0, g1); unpack2f(l1.y, g2, g3);
        a0 += f0 + g0; a1 += f1 + g1; a2 += f2 + g2; a3 += f3 + g3;
    }
    for (; p < end; ++p) {
        int s0 = g_col[p];
        uint2 h0 = xh[(long long)s0 * 32 + lane];
        uint2 l0 = xl[(long long)s0 * 32 + lane];
        float f0, f1, f2, f3, g0, g1, g2, g3;
        unpack2f(h0.x, f0, f1); unpack2f(h0.y, f2, f3);
        unpack2f(l0.x, g0, g1); unpack2f(l0.y, g2, g3);
        a0 += f0 + g0; a1 += f1 + g1; a2 += f2 + g2; a3 += f3 + g3;
    }
    float inv = g_inv[w];
    a0 *= inv; a1 *= inv; a2 *= inv; a3 *= inv;
    __nv_bfloat16 h0, l0, h1, l1, h2, l2, h3, l3;
    split2(a0, h0, l0); split2(a1, h1, l1);
    split2(a2, h2, l2); split2(a3, h3, l3);
    size_t off = (size_t)w * DIN + lane * 4;
    *(uint2*)&g_a1h[off] = make_uint2(pack_bf16x2(h0, h1), pack_bf16x2(h2, h3));
    *(uint2*)&g_a1l[off] = make_uint2(pack_bf16x2(l0, l1), pack_bf16x2(l2, l3));
}

// ================= bf16x3 HMMA GEMM, cp.async double-buffered ===================
#define SM_LD 40
#define TILE_B (128 * SM_LD * 2)
#define BUF_B  (4 * TILE_B)
#define SMEM_TOTAL (2 * BUF_B)   // 81920 B

static __device__ __forceinline__ void cp16(uint32_t dst, const void* src) {
    asm volatile("cp.async.cg.shared.global [%0], [%1], 16;" :: "r"(dst), "l"(src));
}
static __device__ __forceinline__ void cp_commit() {
    asm volatile("cp.async.commit_group;");
}
template<int N> static __device__ __forceinline__ void cp_wait() {
    asm volatile("cp.async.wait_group %0;" :: "n"(N));
}
static __device__ __forceinline__ void cp_tile(
    uint32_t dst_tile, const __nv_bfloat16* src0, int rowbytes, int tid)
{
    const char* src = (const char*)src0;
#pragma unroll
    for (int r = 0; r < 2; ++r) {
        int c = tid + r * 256;
        int row = c >> 2, seg = c & 3;
        cp16(dst_tile + row * (SM_LD * 2) + seg * 16,
             src + (size_t)row * rowbytes + seg * 16);
    }
}
static __device__ __forceinline__ void lds_x4(uint32_t addr, uint32_t& r0, uint32_t& r1,
                                              uint32_t& r2, uint32_t& r3) {
    asm volatile("ldmatrix.sync.aligned.m8n8.x4.shared.b16 {%0,%1,%2,%3}, [%4];\n"
                 : "=r"(r0), "=r"(r1), "=r"(r2), "=r"(r3) : "r"(addr));
}
static __device__ __forceinline__ void mma_bf16(float* c, const uint32_t* a, uint32_t b0, uint32_t b1) {
    asm volatile(
        "mma.sync.aligned.m16n8k16.row.col.f32.bf16.bf16.f32 "
        "{%0,%1,%2,%3}, {%4,%5,%6,%7}, {%8,%9}, {%0,%1,%2,%3};\n"
        : "+f"(c[0]), "+f"(c[1]), "+f"(c[2]), "+f"(c[3])
        : "r"(a[0]), "r"(a[1]), "r"(a[2]), "r"(a[3]), "r"(b0), "r"(b1));
}
static __device__ __forceinline__ void mma_k16(
    float (&c)[2][8][4], uint32_t Ahi, uint32_t Alo, uint32_t Bhi, uint32_t Blo,
    int m_local, int n_local, int lane, int k16)
{
    const int aRow = (lane & 7) + ((lane >> 3) & 1) * 8;
    const int aCol = k16 + (lane >> 4) * 8;
    const int bRow = (lane & 7) + ((lane >> 4) & 1) * 8;
    const int bCol = k16 + ((lane >> 3) & 1) * 8;

    uint32_t ah[2][4], al[2][4], bh[4][4], bl[4][4];
#pragma unroll
    for (int i = 0; i < 2; ++i)
        lds_x4(Ahi + ((m_local + 16 * i + aRow) * SM_LD + aCol) * 2,
               ah[i][0], ah[i][1], ah[i][2], ah[i][3]);
#pragma unroll
    for (int jj = 0; jj < 4; ++jj)
        lds_x4(Bhi + ((n_local + 16 * jj + bRow) * SM_LD + bCol) * 2,
               bh[jj][0], bh[jj][1], bh[jj][2], bh[jj][3]);
#pragma unroll
    for (int i = 0; i < 2; ++i)
#pragma unroll
        for (int j = 0; j < 8; ++j)
            mma_bf16(c[i][j], ah[i], bh[j >> 1][(j & 1) * 2], bh[j >> 1][(j & 1) * 2 + 1]);
#pragma unroll
    for (int jj = 0; jj < 4; ++jj)
        lds_x4(Blo + ((n_local + 16 * jj + bRow) * SM_LD + bCol) * 2,
               bl[jj][0], bl[jj][1], bl[jj][2], bl[jj][3]);
#pragma unroll
    for (int i = 0; i < 2; ++i)
#pragma unroll
        for (int j = 0; j < 8; ++j)
            mma_bf16(c[i][j], ah[i], bl[j >> 1][(j & 1) * 2], bl[j >> 1][(j & 1) * 2 + 1]);
#pragma unroll
    for (int i = 0; i < 2; ++i)
        lds_x4(Alo + ((m_local + 16 * i + aRow) * SM_LD + aCol) * 2,
               al[i][0], al[i][1], al[i][2], al[i][3]);
#pragma unroll
    for (int i = 0; i < 2; ++i)
#pragma unroll
        for (int j = 0; j < 8; ++j)
            mma_bf16(c[i][j], al[i], bh[j >> 1][(j & 1) * 2], bh[j >> 1][(j & 1) * 2 + 1]);
}
static __device__ __forceinline__ void issue_chunk(
    uint32_t smb, int buf, const __nv_bfloat16* Ah, const __nv_bfloat16* Al,
    const __nv_bfloat16* Bh, const __nv_bfloat16* Bl, int ldkB, int tid)
{
    uint32_t b = smb + buf * BUF_B;
    cp_tile(b,              Ah, ldkB, tid);
    cp_tile(b + TILE_B,     Al, ldkB, tid);
    cp_tile(b + 2 * TILE_B, Bh, ldkB, tid);
    cp_tile(b + 3 * TILE_B, Bl, ldkB, tid);
    cp_commit();
}
#define GEMM_LOOP(NCH, GET_A_H, GET_A_L, GET_B_H, GET_B_L, LDKB)                 \
    issue_chunk(smb, 0, GET_A_H(0), GET_A_L(0), GET_B_H(0), GET_B_L(0), LDKB, tid); \
    for (int ch = 0; ch < (NCH); ++ch) {                                          \
        int cur = ch & 1;                                                         \
        if (ch + 1 < (NCH)) {                                                     \
            issue_chunk(smb, cur ^ 1, GET_A_H(ch + 1), GET_A_L(ch + 1),           \
                        GET_B_H(ch + 1), GET_B_L(ch + 1), LDKB, tid);             \
            cp_wait<1>();                                                         \
        } else {                                                                  \
            cp_wait<0>();                                                         \
        }                                                                         \
        __syncthreads();                                                          \
        uint32_t b = smb + cur * BUF_B;                                           \
        mma_k16(c, b, b + TILE_B, b + 2 * TILE_B, b + 3 * TILE_B,                 \
                m_local, n_local, lane, 0);                                       \
        mma_k16(c, b, b + TILE_B, b + 2 * TILE_B, b + 3 * TILE_B,                 \
                m_local, n_local, lane, 16);                                      \
        __syncthreads();                                                          \
    }

// Layer 1: h = relu( agg1 @ W1l^T + x @ W1r^T + b1 ) -> g_hh/g_hl   grid(392, 2)
__global__ void __launch_bounds__(256)
gemm1_mma_kernel(const float* __restrict__ b1) {
    extern __shared__ char sm[];
    uint32_t smb = (uint32_t)__cvta_generic_to_shared(sm);
    const int tid = threadIdx.x, lane = tid & 31, wid = tid >> 5;
    const int m_local = (wid & 3) * 32;
    const int n_local = (wid >> 2) * 64;
    const int m0 = blockIdx.x * 128;
    const int n0 = blockIdx.y * 128;

    float c[2][8][4];
#pragma unroll
    for (int i = 0; i < 2; ++i)
#pragma unroll
        for (int j = 0; j < 8; ++j)
#pragma unroll
            for (int k = 0; k < 4; ++k) c[i][j][k] = 0.f;

#define GA_H(ch) (((ch) < 4 ? g_a1h : g_xh) + (size_t)m0 * DIN + ((ch) & 3) * 32)
#define GA_L(ch) (((ch) < 4 ? g_a1l : g_xl) + (size_t)m0 * DIN + ((ch) & 3) * 32)
#define GB_H(ch) (g_w1h + (size_t)(((ch) < 4 ? 0 : 256) + n0) * DIN + ((ch) & 3) * 32)
#define GB_L(ch) (g_w1l + (size_t)(((ch) < 4 ? 0 : 256) + n0) * DIN + ((ch) & 3) * 32)
    GEMM_LOOP(8, GA_H, GA_L, GB_H, GB_L, DIN * 2)
#undef GA_H
#undef GA_L
#undef GB_H
#undef GB_L

    const int gid = lane >> 2, tig = lane & 3;
#pragma unroll
    for (int i = 0; i < 2; ++i) {
        int row = m0 + m_local + 16 * i + gid;
#pragma unroll
        for (int j = 0; j < 8; ++j) {
            int col = n0 + n_local + 8 * j + 2 * tig;
            float bb0 = b1[col], bb1 = b1[col + 1];
            if (row < N_NODES) {
                float v0 = fmaxf(c[i][j][0] + bb0, 0.f);
                float v1 = fmaxf(c[i][j][1] + bb1, 0.f);
                __nv_bfloat16 h0, l0, h1, l1;
                split2(v0, h0, l0); split2(v1, h1, l1);
                *(uint32_t*)&g_hh[(size_t)row * DH + col] = pack_bf16x2(h0, h1);
                *(uint32_t*)&g_hl[(size_t)row * DH + col] = pack_bf16x2(l0, l1);
            }
            if (row + 8 < N_NODES) {
                float v0 = fmaxf(c[i][j][2] + bb0, 0.f);
                float v1 = fmaxf(c[i][j][3] + bb1, 0.f);
                __nv_bfloat16 h0, l0, h1, l1;
                split2(v0, h0, l0); split2(v1, h1, l1);
                *(uint32_t*)&g_hh[(size_t)(row + 8) * DH + col] = pack_bf16x2(h0, h1);
                *(uint32_t*)&g_hl[(size_t)(row + 8) * DH + col] = pack_bf16x2(l0, l1);
            }
        }
    }
}

// gemm2: P = h @ [W2l;W2r]^T -> g_P (fp32)   grid(392, 1), K=256
__global__ void __launch_bounds__(256)
gemm2_mma_kernel() {
    extern __shared__ char sm[];
    uint32_t smb = (uint32_t)__cvta_generic_to_shared(sm);
    const int tid = threadIdx.x, lane = tid & 31, wid = tid >> 5;
    const int m_local = (wid & 3) * 32;
    const int n_local = (wid >> 2) * 64;
    const int m0 = blockIdx.x * 128;

    float c[2][8][4];
#pragma unroll
    for (int i = 0; i < 2; ++i)
#pragma unroll
        for (int j = 0; j < 8; ++j)
#pragma unroll
            for (int k = 0; k < 4; ++k) c[i][j][k] = 0.f;

#define HA_H(ch) (g_hh + (size_t)m0 * DH + (ch) * 32)
#define HA_L(ch) (g_hl + (size_t)m0 * DH + (ch) * 32)
#define HB_H(ch) (g_w2h + (ch) * 32)
#define HB_L(ch) (g_w2l + (ch) * 32)
    GEMM_LOOP(8, HA_H, HA_L, HB_H, HB_L, DH * 2)
#undef HA_H
#undef HA_L
#undef HB_H
#undef HB_L

    const int gid = lane >> 2, tig = lane & 3;
#pragma unroll
    for (int i = 0; i < 2; ++i) {
        int row = m0 + m_local + 16 * i + gid;
#pragma unroll
        for (int j = 0; j < 8; ++j) {
            int col = n_local + 8 * j + 2 * tig;
            if (row < N_NODES)
                *(float2*)&g_P[(size_t)row * 2 * DOUT + col] =
                    make_float2(c[i][j][0], c[i][j][1]);
            if (row + 8 < N_NODES)
                *(float2*)&g_P[(size_t)(row + 8) * 2 * DOUT + col] =
                    make_float2(c[i][j][2], c[i][j][3]);
        }
    }
}

// ---- layer-2 aggregation + combine (gather, warp per node; R12 form) ----------
__global__ void __launch_bounds__(256)
agg2_final_kernel(const float* __restrict__ b2, float* __restrict__ out) {
    int w    = (blockIdx.x * blockDim.x + threadIdx.x) >> 5;
    int lane = threadIdx.x & 31;
    if (w >= N_NODES) return;
    int start = g_rowptr[w], end = g_rowptr[w + 1];
    const float2* Pv = (const float2*)g_P;
    float2 acc = make_float2(0.f, 0.f);
    int p = start;
    for (; p + 4 <= end; p += 4) {
        int s0 = g_col[p], s1 = g_col[p + 1], s2 = g_col[p + 2], s3 = g_col[p + 3];
        float2 v0 = Pv[(long long)s0 * 64 + lane];
        float2 v1 = Pv[(long long)s1 * 64 + lane];
        float2 v2 = Pv[(long long)s2 * 64 + lane];
        float2 v3 = Pv[(long long)s3 * 64 + lane];
        acc.x += v0.x + v1.x + v2.x + v3.x;
        acc.y += v0.y + v1.y + v2.y + v3.y;
    }
    for (; p < end; ++p) {
        float2 v = Pv[(long long)g_col[p] * 64 + lane];
        acc.x += v.x; acc.y += v.y;
    }
    float inv = g_inv[w];
    float2 root = Pv[(long long)w * 64 + 32 + lane];
    float2 bias = ((const float2*)b2)[lane];
    float2 o;
    o.x = acc.x * inv + root.x + bias.x;
    o.y = acc.y * inv + root.y + bias.y;
    ((float2*)out)[(long long)w * 32 + lane] = o;
}

// ---------------- launch --------------------------------------------------------
extern "C" void kernel_launch(void* const* d_in, const int* in_sizes, int n_in,
                              void* d_out, int out_size) {
    const float* x   = (const float*)d_in[0];
    const void*  ei  = d_in[1];
    const float* W1l = (const float*)d_in[2];
    const float* W1r = (const float*)d_in[3];
    const float* b1  = (const float*)d_in[4];
    const float* W2l = (const float*)d_in[5];
    const float* W2r = (const float*)d_in[6];
    const float* b2  = (const float*)d_in[7];
    float*       out = (float*)d_out;

    cudaFuncSetAttribute(gemm1_mma_kernel,
                         cudaFuncAttributeMaxDynamicSharedMemorySize, SMEM_TOTAL);
    cudaFuncSetAttribute(gemm2_mma_kernel,
                         cudaFuncAttributeMaxDynamicSharedMemorySize, SMEM_TOTAL);

    {
        const int total = N_NODES * (DIN / 4) + 512 * DIN + 128 * DH + N_NODES;
        prep_kernel<<<(total + 255) / 256, 256>>>(x, W1l, W1r, W2l, W2r,
                                                  (const unsigned int*)ei);
    }
    count_kernel<<<(N_EDGES / 4 + 255) / 256, 256>>>(ei);
    blocksum_kernel<<<NB_SCAN, 256>>>();
    rowptr_kernel<<<NB_SCAN, 256>>>();
    fill_kernel<<<(N_EDGES / 2 + 255) / 256, 256>>>(ei);
    agg1_kernel<<<(N_NODES * 32 + 255) / 256, 256>>>();
    {
        dim3 grid(N_PAD / 128, 2);
        gemm1_mma_kernel<<<grid, 256, SMEM_TOTAL>>>(b1);
    }
    {
        dim3 grid(N_PAD / 128, 1);
        gemm2_mma_kernel<<<grid, 256, SMEM_TOTAL>>>();
    }
    agg2_final_kernel<<<(N_NODES * 32 + 255) / 256, 256>>>(b2, out);
}

// round 15
// speedup vs baseline: 1.0469x; 1.0469x over previous
#include <cuda_runtime.h>
#include <cuda_bf16.h>
#include <cstdint>

#define N_NODES 50000
#define N_PAD   50176   // 392 * 128
#define N_EDGES 800000
#define DIN 128
#define DH  256
#define DOUT 64
#define NB_SCAN 49

// ---------------- scratch ------------------------------------------------------
__device__ __align__(16) float g_inv [N_NODES];
__device__ __align__(16) float g_P   [N_NODES * 2*DOUT];
__device__ __align__(16) __nv_bfloat16 g_a1h[N_PAD * DIN];
__device__ __align__(16) __nv_bfloat16 g_a1l[N_PAD * DIN];
__device__ __align__(16) __nv_bfloat16 g_xh [N_PAD * DIN];
__device__ __align__(16) __nv_bfloat16 g_xl [N_PAD * DIN];
__device__ __align__(16) __nv_bfloat16 g_hh [N_PAD * DH];
__device__ __align__(16) __nv_bfloat16 g_hl [N_PAD * DH];
__device__ __align__(16) __nv_bfloat16 g_w1h[512 * DIN];  // 0..255 W1l, 256..511 W1r
__device__ __align__(16) __nv_bfloat16 g_w1l[512 * DIN];
__device__ __align__(16) __nv_bfloat16 g_w2h[128 * DH];   // 0..63 W2l, 64..127 W2r
__device__ __align__(16) __nv_bfloat16 g_w2l[128 * DH];
__device__ int g_rowptr[N_NODES + 1];
__device__ int g_cnt   [N_NODES];
__device__ int g_col   [N_EDGES];
__device__ int g_bsum  [64];
__device__ int g_is64;

static __device__ __forceinline__ uint32_t pack_bf16x2(__nv_bfloat16 a, __nv_bfloat16 b) {
    return (uint32_t)__bfloat16_as_ushort(a) | ((uint32_t)__bfloat16_as_ushort(b) << 16);
}
static __device__ __forceinline__ void split2(float v, __nv_bfloat16& h, __nv_bfloat16& l) {
    h = __float2bfloat16(v);
    l = __float2bfloat16(v - __bfloat162float(h));
}

// ---------------- prep: split_x + split_w + zero counts + detect (fused) -------
__global__ void prep_kernel(const float* __restrict__ x,
                            const float* __restrict__ W1l, const float* __restrict__ W1r,
                            const float* __restrict__ W2l, const float* __restrict__ W2r,
                            const unsigned int* __restrict__ ei_words) {
    const int NX = N_NODES * (DIN / 4);   // 1,600,000 float4 units
    const int T1 = 512 * DIN;             // 65536
    const int T2 = 128 * DH;              // 32768
    int idx = blockIdx.x * blockDim.x + threadIdx.x;
    if (idx < NX) {
        float4 v = ((const float4*)x)[idx];
        __nv_bfloat16 h0, l0, h1, l1, h2, l2, h3, l3;
        split2(v.x, h0, l0); split2(v.y, h1, l1);
        split2(v.z, h2, l2); split2(v.w, h3, l3);
        *(uint2*)&g_xh[idx * 4] = make_uint2(pack_bf16x2(h0, h1), pack_bf16x2(h2, h3));
        *(uint2*)&g_xl[idx * 4] = make_uint2(pack_bf16x2(l0, l1), pack_bf16x2(l2, l3));
    } else if (idx < NX + T1) {
        int j = idx - NX;
        int row = j >> 7, col = j & 127;
        float v = (row < 256) ? W1l[row * DIN + col] : W1r[(row - 256) * DIN + col];
        __nv_bfloat16 h, l; split2(v, h, l);
        g_w1h[j] = h; g_w1l[j] = l;
    } else if (idx < NX + T1 + T2) {
        int j = idx - NX - T1;
        int row = j >> 8, col = j & 255;
        float v = (row < DOUT) ? W2l[row * DH + col] : W2r[(row - DOUT) * DH + col];
        __nv_bfloat16 h, l; split2(v, h, l);
        g_w2h[j] = h; g_w2l[j] = l;
    } else if (idx < NX + T1 + T2 + N_NODES) {
        g_cnt[idx - NX - T1 - T2] = 0;
    }
    if (idx == 0) {
        int is64 = 1;
        for (int k = 0; k < 128; ++k)
            if (ei_words[2 * k + 1] != 0u) { is64 = 0; break; }
        g_is64 = is64;
    }
}
__device__ __forceinline__ long long edge_val(const void* ei, long long idx) {
    if (g_is64) return ((const long long*)ei)[idx];
    return (long long)((const int*)ei)[idx];
}

// 4 edges per thread, wide loads (800000 % 4 == 0, no tail)
__global__ void count_kernel(const void* __restrict__ ei) {
    int t = blockIdx.x * blockDim.x + threadIdx.x;
    int e0 = t * 4;
    if (e0 >= N_EDGES) return;
    long long d[4];
    if (g_is64) {
        const longlong2* p = (const longlong2*)((const long long*)ei + N_EDGES + e0);
        longlong2 a = p[0], b = p[1];
        d[0] = a.x; d[1] = a.y; d[2] = b.x; d[3] = b.y;
    } else {
        int4 a = *(const int4*)((const int*)ei + N_EDGES + e0);
        d[0] = a.x; d[1] = a.y; d[2] = a.z; d[3] = a.w;
    }
#pragma unroll
    for (int k = 0; k < 4; ++k)
        if ((unsigned long long)d[k] < N_NODES) atomicAdd(&g_cnt[(int)d[k]], 1);
}
__global__ void blocksum_kernel() {
    int b = blockIdx.x, t = threadIdx.x;
    int i0 = b * 1024 + t * 4;
    int s = 0;
#pragma unroll
    for (int k = 0; k < 4; ++k) { int i = i0 + k; if (i < N_NODES) s += g_cnt[i]; }
    for (int off = 16; off > 0; off >>= 1) s += __shfl_down_sync(0xffffffffu, s, off);
    __shared__ int ws[8];
    int lane = t & 31, w = t >> 5;
    if (lane == 0) ws[w] = s;
    __syncthreads();
    if (t == 0) { int tot = 0; for (int k = 0; k < 8; ++k) tot += ws[k]; g_bsum[b] = tot; }
}
// rowptr: per-block scan + inline prefix over g_bsum
__global__ void rowptr_kernel() {
    __shared__ int warp_tot[8];
    __shared__ int warp_off[8];
    __shared__ int s_boff;
    int b = blockIdx.x, t = threadIdx.x;
    int lane = t & 31, w = t >> 5;
    int i0 = b * 1024 + t * 4;
    int c[4];
#pragma unroll
    for (int k = 0; k < 4; ++k) { int i = i0 + k; c[k] = (i < N_NODES) ? g_cnt[i] : 0; }
    int s = c[0] + c[1] + c[2] + c[3];
    int pre = s;
    for (int off = 1; off < 32; off <<= 1) {
        int n = __shfl_up_sync(0xffffffffu, pre, off);
        if (lane >= off) pre += n;
    }
    if (lane == 31) warp_tot[w] = pre;
    if (t == 0) {
        int off = 0;
        for (int k = 0; k < b; ++k) off += g_bsum[k];
        s_boff = off;
    }
    __syncthreads();
    if (w == 0) {
        int v = (lane < 8) ? warp_tot[lane] : 0;
        int orig = v;
        for (int off = 1; off < 8; off <<= 1) {
            int n = __shfl_up_sync(0xffffffffu, v, off);
            if (lane >= off) v += n;
        }
        if (lane < 8) warp_off[lane] = v - orig;
    }
    __syncthreads();
    int r = s_boff + warp_off[w] + (pre - s);
#pragma unroll
    for (int k = 0; k < 4; ++k) {
        int i = i0 + k;
        if (i < N_NODES) {
            g_rowptr[i] = r;
            g_cnt[i]    = r;   // fill cursor
            g_inv[i]    = 1.0f / (float)(c[k] > 0 ? c[k] : 1);
            r += c[k];
            if (i == N_NODES - 1) g_rowptr[N_NODES] = r;
        }
    }
}
// 2 edges per thread, wide loads (800000 % 2 == 0)
__global__ void fill_kernel(const void* __restrict__ ei) {
    int t = blockIdx.x * blockDim.x + threadIdx.x;
    int e0 = t * 2;
    if (e0 >= N_EDGES) return;
    long long s0, s1, d0, d1;
    if (g_is64) {
        longlong2 sp = *(const longlong2*)((const long long*)ei + e0);
        longlong2 dp = *(const longlong2*)((const long long*)ei + N_EDGES + e0);
        s0 = sp.x; s1 = sp.y; d0 = dp.x; d1 = dp.y;
    } else {
        int2 sp = *(const int2*)((const int*)ei + e0);
        int2 dp = *(const int2*)((const int*)ei + N_EDGES + e0);
        s0 = sp.x; s1 = sp.y; d0 = dp.x; d1 = dp.y;
    }
    if ((unsigned long long)s0 < N_NODES && (unsigned long long)d0 < N_NODES) {
        int pos = atomicAdd(&g_cnt[(int)d0], 1);
        g_col[pos] = (int)s0;
    }
    if ((unsigned long long)s1 < N_NODES && (unsigned long long)d1 < N_NODES) {
        int pos = atomicAdd(&g_cnt[(int)d1], 1);
        g_col[pos] = (int)s1;
    }
}

// ---------------- layer-1 aggregation (gather, warp per node, fp32 float4) -----
__global__ void __launch_bounds__(256)
agg1_kernel(const float* __restrict__ x) {
    int w    = (blockIdx.x * blockDim.x + threadIdx.x) >> 5;
    int lane = threadIdx.x & 31;
    if (w >= N_NODES) return;
    int start = g_rowptr[w], end = g_rowptr[w + 1];
    const float4* xv = (const float4*)x;
    float4 acc = make_float4(0.f, 0.f, 0.f, 0.f);
    int p = start;
    for (; p + 4 <= end; p += 4) {
        int s0 = g_col[p], s1 = g_col[p + 1], s2 = g_col[p + 2], s3 = g_col[p + 3];
        float4 v0 = xv[(long long)s0 * 32 + lane];
        float4 v1 = xv[(long long)s1 * 32 + lane];
        float4 v2 = xv[(long long)s2 * 32 + lane];
        float4 v3 = xv[(long long)s3 * 32 + lane];
        acc.x += v0.x + v1.x + v2.x + v3.x;
        acc.y += v0.y + v1.y + v2.y + v3.y;
        acc.z += v0.z + v1.z + v2.z + v3.z;
        acc.w += v0.w + v1.w + v2.w + v3.w;
    }
    for (; p < end; ++p) {
        float4 v = xv[(long long)g_col[p] * 32 + lane];
        acc.x += v.x; acc.y += v.y; acc.z += v.z; acc.w += v.w;
    }
    float inv = g_inv[w];
    acc.x *= inv; acc.y *= inv; acc.z *= inv; acc.w *= inv;
    __nv_bfloat16 h0, l0, h1, l1, h2, l2, h3, l3;
    split2(acc.x, h0, l0); split2(acc.y, h1, l1);
    split2(acc.z, h2, l2); split2(acc.w, h3, l3);
    size_t off = (size_t)w * DIN + lane * 4;
    *(uint2*)&g_a1h[off] = make_uint2(pack_bf16x2(h0, h1), pack_bf16x2(h2, h3));
    *(uint2*)&g_a1l[off] = make_uint2(pack_bf16x2(l0, l1), pack_bf16x2(l2, l3));
}

// ================= bf16x3 HMMA GEMM, cp.async double-buffered ===================
#define SM_LD 40
#define TILE_B (128 * SM_LD * 2)
#define BUF_B  (4 * TILE_B)
#define SMEM_TOTAL (2 * BUF_B)   // 81920 B

static __device__ __forceinline__ void cp16(uint32_t dst, const void* src) {
    asm volatile("cp.async.cg.shared.global [%0], [%1], 16;" :: "r"(dst), "l"(src));
}
static __device__ __forceinline__ void cp_commit() {
    asm volatile("cp.async.commit_group;");
}
template<int N> static __device__ __forceinline__ void cp_wait() {
    asm volatile("cp.async.wait_group %0;" :: "n"(N));
}
static __device__ __forceinline__ void cp_tile(
    uint32_t dst_tile, const __nv_bfloat16* src0, int rowbytes, int tid)
{
    const char* src = (const char*)src0;
#pragma unroll
    for (int r = 0; r < 2; ++r) {
        int c = tid + r * 256;
        int row = c >> 2, seg = c & 3;
        cp16(dst_tile + row * (SM_LD * 2) + seg * 16,
             src + (size_t)row * rowbytes + seg * 16);
    }
}
static __device__ __forceinline__ void lds_x4(uint32_t addr, uint32_t& r0, uint32_t& r1,
                                              uint32_t& r2, uint32_t& r3) {
    asm volatile("ldmatrix.sync.aligned.m8n8.x4.shared.b16 {%0,%1,%2,%3}, [%4];\n"
                 : "=r"(r0), "=r"(r1), "=r"(r2), "=r"(r3) : "r"(addr));
}
static __device__ __forceinline__ void mma_bf16(float* c, const uint32_t* a, uint32_t b0, uint32_t b1) {
    asm volatile(
        "mma.sync.aligned.m16n8k16.row.col.f32.bf16.bf16.f32 "
        "{%0,%1,%2,%3}, {%4,%5,%6,%7}, {%8,%9}, {%0,%1,%2,%3};\n"
        : "+f"(c[0]), "+f"(c[1]), "+f"(c[2]), "+f"(c[3])
        : "r"(a[0]), "r"(a[1]), "r"(a[2]), "r"(a[3]), "r"(b0), "r"(b1));
}
static __device__ __forceinline__ void mma_k16(
    float (&c)[2][8][4], uint32_t Ahi, uint32_t Alo, uint32_t Bhi, uint32_t Blo,
    int m_local, int n_local, int lane, int k16)
{
    const int aRow = (lane & 7) + ((lane >> 3) & 1) * 8;
    const int aCol = k16 + (lane >> 4) * 8;
    const int bRow = (lane & 7) + ((lane >> 4) & 1) * 8;
    const int bCol = k16 + ((lane >> 3) & 1) * 8;

    uint32_t ah[2][4], al[2][4], bh[4][4], bl[4][4];
#pragma unroll
    for (int i = 0; i < 2; ++i)
        lds_x4(Ahi + ((m_local + 16 * i + aRow) * SM_LD + aCol) * 2,
               ah[i][0], ah[i][1], ah[i][2], ah[i][3]);
#pragma unroll
    for (int jj = 0; jj < 4; ++jj)
        lds_x4(Bhi + ((n_local + 16 * jj + bRow) * SM_LD + bCol) * 2,
               bh[jj][0], bh[jj][1], bh[jj][2], bh[jj][3]);
#pragma unroll
    for (int i = 0; i < 2; ++i)
#pragma unroll
        for (int j = 0; j < 8; ++j)
            mma_bf16(c[i][j], ah[i], bh[j >> 1][(j & 1) * 2], bh[j >> 1][(j & 1) * 2 + 1]);
#pragma unroll
    for (int jj = 0; jj < 4; ++jj)
        lds_x4(Blo + ((n_local + 16 * jj + bRow) * SM_LD + bCol) * 2,
               bl[jj][0], bl[jj][1], bl[jj][2], bl[jj][3]);
#pragma unroll
    for (int i = 0; i < 2; ++i)
#pragma unroll
        for (int j = 0; j < 8; ++j)
            mma_bf16(c[i][j], ah[i], bl[j >> 1][(j & 1) * 2], bl[j >> 1][(j & 1) * 2 + 1]);
#pragma unroll
    for (int i = 0; i < 2; ++i)
        lds_x4(Alo + ((m_local + 16 * i + aRow) * SM_LD + aCol) * 2,
               al[i][0], al[i][1], al[i][2], al[i][3]);
#pragma unroll
    for (int i = 0; i < 2; ++i)
#pragma unroll
        for (int j = 0; j < 8; ++j)
            mma_bf16(c[i][j], al[i], bh[j >> 1][(j & 1) * 2], bh[j >> 1][(j & 1) * 2 + 1]);
}
static __device__ __forceinline__ void issue_chunk(
    uint32_t smb, int buf, const __nv_bfloat16* Ah, const __nv_bfloat16* Al,
    const __nv_bfloat16* Bh, const __nv_bfloat16* Bl, int ldkB, int tid)
{
    uint32_t b = smb + buf * BUF_B;
    cp_tile(b,              Ah, ldkB, tid);
    cp_tile(b + TILE_B,     Al, ldkB, tid);
    cp_tile(b + 2 * TILE_B, Bh, ldkB, tid);
    cp_tile(b + 3 * TILE_B, Bl, ldkB, tid);
    cp_commit();
}
#define GEMM_LOOP(NCH, GET_A_H, GET_A_L, GET_B_H, GET_B_L, LDKB)                 \
    issue_chunk(smb, 0, GET_A_H(0), GET_A_L(0), GET_B_H(0), GET_B_L(0), LDKB, tid); \
    for (int ch = 0; ch < (NCH); ++ch) {                                          \
        int cur = ch & 1;                                                         \
        if (ch + 1 < (NCH)) {                                                     \
            issue_chunk(smb, cur ^ 1, GET_A_H(ch + 1), GET_A_L(ch + 1),           \
                        GET_B_H(ch + 1), GET_B_L(ch + 1), LDKB, tid);             \
            cp_wait<1>();                                                         \
        } else {                                                                  \
            cp_wait<0>();                                                         \
        }                                                                         \
        __syncthreads();                                                          \
        uint32_t b = smb + cur * BUF_B;                                           \
        mma_k16(c, b, b + TILE_B, b + 2 * TILE_B, b + 3 * TILE_B,                 \
                m_local, n_local, lane, 0);                                       \
        mma_k16(c, b, b + TILE_B, b + 2 * TILE_B, b + 3 * TILE_B,                 \
                m_local, n_local, lane, 16);                                      \
        __syncthreads();                                                          \
    }

// Layer 1: h = relu( agg1 @ W1l^T + x @ W1r^T + b1 ) -> g_hh/g_hl   grid(392, 2)
__global__ void __launch_bounds__(256)
gemm1_mma_kernel(const float* __restrict__ b1) {
    extern __shared__ char sm[];
    uint32_t smb = (uint32_t)__cvta_generic_to_shared(sm);
    const int tid = threadIdx.x, lane = tid & 31, wid = tid >> 5;
    const int m_local = (wid & 3) * 32;
    const int n_local = (wid >> 2) * 64;
    const int m0 = blockIdx.x * 128;
    const int n0 = blockIdx.y * 128;

    float c[2][8][4];
#pragma unroll
    for (int i = 0; i < 2; ++i)
#pragma unroll
        for (int j = 0; j < 8; ++j)
#pragma unroll
            for (int k = 0; k < 4; ++k) c[i][j][k] = 0.f;

#define GA_H(ch) (((ch) < 4 ? g_a1h : g_xh) + (size_t)m0 * DIN + ((ch) & 3) * 32)
#define GA_L(ch) (((ch) < 4 ? g_a1l : g_xl) + (size_t)m0 * DIN + ((ch) & 3) * 32)
#define GB_H(ch) (g_w1h + (size_t)(((ch) < 4 ? 0 : 256) + n0) * DIN + ((ch) & 3) * 32)
#define GB_L(ch) (g_w1l + (size_t)(((ch) < 4 ? 0 : 256) + n0) * DIN + ((ch) & 3) * 32)
    GEMM_LOOP(8, GA_H, GA_L, GB_H, GB_L, DIN * 2)
#undef GA_H
#undef GA_L
#undef GB_H
#undef GB_L

    const int gid = lane >> 2, tig = lane & 3;
#pragma unroll
    for (int i = 0; i < 2; ++i) {
        int row = m0 + m_local + 16 * i + gid;
#pragma unroll
        for (int j = 0; j < 8; ++j) {
            int col = n0 + n_local + 8 * j + 2 * tig;
            float bb0 = b1[col], bb1 = b1[col + 1];
            if (row < N_NODES) {
                float v0 = fmaxf(c[i][j][0] + bb0, 0.f);
                float v1 = fmaxf(c[i][j][1] + bb1, 0.f);
                __nv_bfloat16 h0, l0, h1, l1;
                split2(v0, h0, l0); split2(v1, h1, l1);
                *(uint32_t*)&g_hh[(size_t)row * DH + col] = pack_bf16x2(h0, h1);
                *(uint32_t*)&g_hl[(size_t)row * DH + col] = pack_bf16x2(l0, l1);
            }
            if (row + 8 < N_NODES) {
                float v0 = fmaxf(c[i][j][2] + bb0, 0.f);
                float v1 = fmaxf(c[i][j][3] + bb1, 0.f);
                __nv_bfloat16 h0, l0, h1, l1;
                split2(v0, h0, l0); split2(v1, h1, l1);
                *(uint32_t*)&g_hh[(size_t)(row + 8) * DH + col] = pack_bf16x2(h0, h1);
                *(uint32_t*)&g_hl[(size_t)(row + 8) * DH + col] = pack_bf16x2(l0, l1);
            }
        }
    }
}

// gemm2: P = h @ [W2l;W2r]^T -> g_P (fp32)   grid(392, 1), K=256
__global__ void __launch_bounds__(256)
gemm2_mma_kernel() {
    extern __shared__ char sm[];
    uint32_t smb = (uint32_t)__cvta_generic_to_shared(sm);
    const int tid = threadIdx.x, lane = tid & 31, wid = tid >> 5;
    const int m_local = (wid & 3) * 32;
    const int n_local = (wid >> 2) * 64;
    const int m0 = blockIdx.x * 128;

    float c[2][8][4];
#pragma unroll
    for (int i = 0; i < 2; ++i)
#pragma unroll
        for (int j = 0; j < 8; ++j)
#pragma unroll
            for (int k = 0; k < 4; ++k) c[i][j][k] = 0.f;

#define HA_H(ch) (g_hh + (size_t)m0 * DH + (ch) * 32)
#define HA_L(ch) (g_hl + (size_t)m0 * DH + (ch) * 32)
#define HB_H(ch) (g_w2h + (ch) * 32)
#define HB_L(ch) (g_w2l + (ch) * 32)
    GEMM_LOOP(8, HA_H, HA_L, HB_H, HB_L, DH * 2)
#undef HA_H
#undef HA_L
#undef HB_H
#undef HB_L

    const int gid = lane >> 2, tig = lane & 3;
#pragma unroll
    for (int i = 0; i < 2; ++i) {
        int row = m0 + m_local + 16 * i + gid;
#pragma unroll
        for (int j = 0; j < 8; ++j) {
            int col = n_local + 8 * j + 2 * tig;
            if (row < N_NODES)
                *(float2*)&g_P[(size_t)row * 2 * DOUT + col] =
                    make_float2(c[i][j][0], c[i][j][1]);
            if (row + 8 < N_NODES)
                *(float2*)&g_P[(size_t)(row + 8) * 2 * DOUT + col] =
                    make_float2(c[i][j][2], c[i][j][3]);
        }
    }
}

// ---- layer-2 aggregation + combine (gather, warp per node) --------------------
__global__ void __launch_bounds__(256)
agg2_final_kernel(const float* __restrict__ b2, float* __restrict__ out) {
    int w    = (blockIdx.x * blockDim.x + threadIdx.x) >> 5;
    int lane = threadIdx.x & 31;
    if (w >= N_NODES) return;
    int start = g_rowptr[w], end = g_rowptr[w + 1];
    const float2* Pv = (const float2*)g_P;
    float2 acc = make_float2(0.f, 0.f);
    int p = start;
    for (; p + 4 <= end; p += 4) {
        int s0 = g_col[p], s1 = g_col[p + 1], s2 = g_col[p + 2], s3 = g_col[p + 3];
        float2 v0 = Pv[(long long)s0 * 64 + lane];
        float2 v1 = Pv[(long long)s1 * 64 + lane];
        float2 v2 = Pv[(long long)s2 * 64 + lane];
        float2 v3 = Pv[(long long)s3 * 64 + lane];
        acc.x += v0.x + v1.x + v2.x + v3.x;
        acc.y += v0.y + v1.y + v2.y + v3.y;
    }
    for (; p < end; ++p) {
        float2 v = Pv[(long long)g_col[p] * 64 + lane];
        acc.x += v.x; acc.y += v.y;
    }
    float inv = g_inv[w];
    float2 root = Pv[(long long)w * 64 + 32 + lane];
    float2 bias = ((const float2*)b2)[lane];
    float2 o;
    o.x = acc.x * inv + root.x + bias.x;
    o.y = acc.y * inv + root.y + bias.y;
    ((float2*)out)[(long long)w * 32 + lane] = o;
}

// ---------------- launch --------------------------------------------------------
extern "C" void kernel_launch(void* const* d_in, const int* in_sizes, int n_in,
                              void* d_out, int out_size) {
    const float* x   = (const float*)d_in[0];
    const void*  ei  = d_in[1];
    const float* W1l = (const float*)d_in[2];
    const float* W1r = (const float*)d_in[3];
    const float* b1  = (const float*)d_in[4];
    const float* W2l = (const float*)d_in[5];
    const float* W2r = (const float*)d_in[6];
    const float* b2  = (const float*)d_in[7];
    float*       out = (float*)d_out;

    cudaFuncSetAttribute(gemm1_mma_kernel,
                         cudaFuncAttributeMaxDynamicSharedMemorySize, SMEM_TOTAL);
    cudaFuncSetAttribute(gemm2_mma_kernel,
                         cudaFuncAttributeMaxDynamicSharedMemorySize, SMEM_TOTAL);

    {
        const int total = N_NODES * (DIN / 4) + 512 * DIN + 128 * DH + N_NODES;
        prep_kernel<<<(total + 255) / 256, 256>>>(x, W1l, W1r, W2l, W2r,
                                                  (const unsigned int*)ei);
    }
    count_kernel<<<(N_EDGES / 4 + 255) / 256, 256>>>(ei);
    blocksum_kernel<<<NB_SCAN, 256>>>();
    rowptr_kernel<<<NB_SCAN, 256>>>();
    fill_kernel<<<(N_EDGES / 2 + 255) / 256, 256>>>(ei);
    agg1_kernel<<<(N_NODES * 32 + 255) / 256, 256>>>(x);
    {
        dim3 grid(N_PAD / 128, 2);
        gemm1_mma_kernel<<<grid, 256, SMEM_TOTAL>>>(b1);
    }
    {
        dim3 grid(N_PAD / 128, 1);
        gemm2_mma_kernel<<<grid, 256, SMEM_TOTAL>>>();
    }
    agg2_final_kernel<<<(N_NODES * 32 + 255) / 256, 256>>>(b2, out);
}

// round 16
// speedup vs baseline: 1.0562x; 1.0089x over previous
#include <cuda_runtime.h>
#include <cuda_bf16.h>
#include <cstdint>

#define N_NODES 50000
#define N_PAD   50176   // 392 * 128
#define N_EDGES 800000
#define DIN 128
#define DH  256
#define DOUT 64
#define NB_SCAN 49

// ---------------- scratch ------------------------------------------------------
__device__ __align__(16) float g_inv [N_NODES];
__device__ __align__(16) float g_P   [N_NODES * 2*DOUT];
__device__ __align__(16) __nv_bfloat16 g_a1h[N_PAD * DIN];
__device__ __align__(16) __nv_bfloat16 g_a1l[N_PAD * DIN];
__device__ __align__(16) __nv_bfloat16 g_xh [N_PAD * DIN];
__device__ __align__(16) __nv_bfloat16 g_xl [N_PAD * DIN];
__device__ __align__(16) __nv_bfloat16 g_hh [N_PAD * DH];
__device__ __align__(16) __nv_bfloat16 g_hl [N_PAD * DH];
__device__ __align__(16) __nv_bfloat16 g_w1h[512 * DIN];  // 0..255 W1l, 256..511 W1r
__device__ __align__(16) __nv_bfloat16 g_w1l[512 * DIN];
__device__ __align__(16) __nv_bfloat16 g_w2h[128 * DH];   // 0..63 W2l, 64..127 W2r
__device__ __align__(16) __nv_bfloat16 g_w2l[128 * DH];
__device__ int g_rowptr[N_NODES + 1];
__device__ int g_cnt   [N_NODES];
__device__ int g_col   [N_EDGES];
__device__ int g_bsum  [64];
__device__ int g_is64;

static __device__ __forceinline__ uint32_t pack_bf16x2(__nv_bfloat16 a, __nv_bfloat16 b) {
    return (uint32_t)__bfloat16_as_ushort(a) | ((uint32_t)__bfloat16_as_ushort(b) << 16);
}
static __device__ __forceinline__ void split2(float v, __nv_bfloat16& h, __nv_bfloat16& l) {
    h = __float2bfloat16(v);
    l = __float2bfloat16(v - __bfloat162float(h));
}

// ---------------- prep: split_x + split_w + zero counts + detect (fused) -------
__global__ void prep_kernel(const float* __restrict__ x,
                            const float* __restrict__ W1l, const float* __restrict__ W1r,
                            const float* __restrict__ W2l, const float* __restrict__ W2r,
                            const unsigned int* __restrict__ ei_words) {
    const int NX = N_NODES * (DIN / 4);   // 1,600,000 float4 units
    const int T1 = 512 * DIN;             // 65536
    const int T2 = 128 * DH;              // 32768
    int idx = blockIdx.x * blockDim.x + threadIdx.x;
    if (idx < NX) {
        float4 v = ((const float4*)x)[idx];
        __nv_bfloat16 h0, l0, h1, l1, h2, l2, h3, l3;
        split2(v.x, h0, l0); split2(v.y, h1, l1);
        split2(v.z, h2, l2); split2(v.w, h3, l3);
        *(uint2*)&g_xh[idx * 4] = make_uint2(pack_bf16x2(h0, h1), pack_bf16x2(h2, h3));
        *(uint2*)&g_xl[idx * 4] = make_uint2(pack_bf16x2(l0, l1), pack_bf16x2(l2, l3));
    } else if (idx < NX + T1) {
        int j = idx - NX;
        int row = j >> 7, col = j & 127;
        float v = (row < 256) ? W1l[row * DIN + col] : W1r[(row - 256) * DIN + col];
        __nv_bfloat16 h, l; split2(v, h, l);
        g_w1h[j] = h; g_w1l[j] = l;
    } else if (idx < NX + T1 + T2) {
        int j = idx - NX - T1;
        int row = j >> 8, col = j & 255;
        float v = (row < DOUT) ? W2l[row * DH + col] : W2r[(row - DOUT) * DH + col];
        __nv_bfloat16 h, l; split2(v, h, l);
        g_w2h[j] = h; g_w2l[j] = l;
    } else if (idx < NX + T1 + T2 + N_NODES) {
        g_cnt[idx - NX - T1 - T2] = 0;
    }
    if (idx == 0) {
        int is64 = 1;
        for (int k = 0; k < 128; ++k)
            if (ei_words[2 * k + 1] != 0u) { is64 = 0; break; }
        g_is64 = is64;
    }
}
__device__ __forceinline__ long long edge_val(const void* ei, long long idx) {
    if (g_is64) return ((const long long*)ei)[idx];
    return (long long)((const int*)ei)[idx];
}

// 4 edges per thread, wide loads (800000 % 4 == 0, no tail)
__global__ void count_kernel(const void* __restrict__ ei) {
    int t = blockIdx.x * blockDim.x + threadIdx.x;
    int e0 = t * 4;
    if (e0 >= N_EDGES) return;
    long long d[4];
    if (g_is64) {
        const longlong2* p = (const longlong2*)((const long long*)ei + N_EDGES + e0);
        longlong2 a = p[0], b = p[1];
        d[0] = a.x; d[1] = a.y; d[2] = b.x; d[3] = b.y;
    } else {
        int4 a = *(const int4*)((const int*)ei + N_EDGES + e0);
        d[0] = a.x; d[1] = a.y; d[2] = a.z; d[3] = a.w;
    }
#pragma unroll
    for (int k = 0; k < 4; ++k)
        if ((unsigned long long)d[k] < N_NODES) atomicAdd(&g_cnt[(int)d[k]], 1);
}
__global__ void blocksum_kernel() {
    int b = blockIdx.x, t = threadIdx.x;
    int i0 = b * 1024 + t * 4;
    int s = 0;
#pragma unroll
    for (int k = 0; k < 4; ++k) { int i = i0 + k; if (i < N_NODES) s += g_cnt[i]; }
    for (int off = 16; off > 0; off >>= 1) s += __shfl_down_sync(0xffffffffu, s, off);
    __shared__ int ws[8];
    int lane = t & 31, w = t >> 5;
    if (lane == 0) ws[w] = s;
    __syncthreads();
    if (t == 0) { int tot = 0; for (int k = 0; k < 8; ++k) tot += ws[k]; g_bsum[b] = tot; }
}
// rowptr: per-block scan + inline prefix over g_bsum
__global__ void rowptr_kernel() {
    __shared__ int warp_tot[8];
    __shared__ int warp_off[8];
    __shared__ int s_boff;
    int b = blockIdx.x, t = threadIdx.x;
    int lane = t & 31, w = t >> 5;
    int i0 = b * 1024 + t * 4;
    int c[4];
#pragma unroll
    for (int k = 0; k < 4; ++k) { int i = i0 + k; c[k] = (i < N_NODES) ? g_cnt[i] : 0; }
    int s = c[0] + c[1] + c[2] + c[3];
    int pre = s;
    for (int off = 1; off < 32; off <<= 1) {
        int n = __shfl_up_sync(0xffffffffu, pre, off);
        if (lane >= off) pre += n;
    }
    if (lane == 31) warp_tot[w] = pre;
    if (t == 0) {
        int off = 0;
        for (int k = 0; k < b; ++k) off += g_bsum[k];
        s_boff = off;
    }
    __syncthreads();
    if (w == 0) {
        int v = (lane < 8) ? warp_tot[lane] : 0;
        int orig = v;
        for (int off = 1; off < 8; off <<= 1) {
            int n = __shfl_up_sync(0xffffffffu, v, off);
            if (lane >= off) v += n;
        }
        if (lane < 8) warp_off[lane] = v - orig;
    }
    __syncthreads();
    int r = s_boff + warp_off[w] + (pre - s);
#pragma unroll
    for (int k = 0; k < 4; ++k) {
        int i = i0 + k;
        if (i < N_NODES) {
            g_rowptr[i] = r;
            g_cnt[i]    = r;   // fill cursor
            g_inv[i]    = 1.0f / (float)(c[k] > 0 ? c[k] : 1);
            r += c[k];
            if (i == N_NODES - 1) g_rowptr[N_NODES] = r;
        }
    }
}
// 2 edges per thread, wide loads (800000 % 2 == 0)
__global__ void fill_kernel(const void* __restrict__ ei) {
    int t = blockIdx.x * blockDim.x + threadIdx.x;
    int e0 = t * 2;
    if (e0 >= N_EDGES) return;
    long long s0, s1, d0, d1;
    if (g_is64) {
        longlong2 sp = *(const longlong2*)((const long long*)ei + e0);
        longlong2 dp = *(const longlong2*)((const long long*)ei + N_EDGES + e0);
        s0 = sp.x; s1 = sp.y; d0 = dp.x; d1 = dp.y;
    } else {
        int2 sp = *(const int2*)((const int*)ei + e0);
        int2 dp = *(const int2*)((const int*)ei + N_EDGES + e0);
        s0 = sp.x; s1 = sp.y; d0 = dp.x; d1 = dp.y;
    }
    if ((unsigned long long)s0 < N_NODES && (unsigned long long)d0 < N_NODES) {
        int pos = atomicAdd(&g_cnt[(int)d0], 1);
        g_col[pos] = (int)s0;
    }
    if ((unsigned long long)s1 < N_NODES && (unsigned long long)d1 < N_NODES) {
        int pos = atomicAdd(&g_cnt[(int)d1], 1);
        g_col[pos] = (int)s1;
    }
}

// ---------------- layer-1 aggregation (gather, warp per node, fp32 float4) -----
__global__ void __launch_bounds__(256)
agg1_kernel(const float* __restrict__ x) {
    int w    = (blockIdx.x * blockDim.x + threadIdx.x) >> 5;
    int lane = threadIdx.x & 31;
    if (w >= N_NODES) return;
    int start = g_rowptr[w], end = g_rowptr[w + 1];
    const float4* xv = (const float4*)x;
    float4 acc = make_float4(0.f, 0.f, 0.f, 0.f);
    int p = start;
    for (; p + 4 <= end; p += 4) {
        int s0 = g_col[p], s1 = g_col[p + 1], s2 = g_col[p + 2], s3 = g_col[p + 3];
        float4 v0 = xv[(long long)s0 * 32 + lane];
        float4 v1 = xv[(long long)s1 * 32 + lane];
        float4 v2 = xv[(long long)s2 * 32 + lane];
        float4 v3 = xv[(long long)s3 * 32 + lane];
        acc.x += v0.x + v1.x + v2.x + v3.x;
        acc.y += v0.y + v1.y + v2.y + v3.y;
        acc.z += v0.z + v1.z + v2.z + v3.z;
        acc.w += v0.w + v1.w + v2.w + v3.w;
    }
    for (; p < end; ++p) {
        float4 v = xv[(long long)g_col[p] * 32 + lane];
        acc.x += v.x; acc.y += v.y; acc.z += v.z; acc.w += v.w;
    }
    float inv = g_inv[w];
    acc.x *= inv; acc.y *= inv; acc.z *= inv; acc.w *= inv;
    __nv_bfloat16 h0, l0, h1, l1, h2, l2, h3, l3;
    split2(acc.x, h0, l0); split2(acc.y, h1, l1);
    split2(acc.z, h2, l2); split2(acc.w, h3, l3);
    size_t off = (size_t)w * DIN + lane * 4;
    *(uint2*)&g_a1h[off] = make_uint2(pack_bf16x2(h0, h1), pack_bf16x2(h2, h3));
    *(uint2*)&g_a1l[off] = make_uint2(pack_bf16x2(l0, l1), pack_bf16x2(l2, l3));
}

// ================= bf16x3 HMMA GEMM, cp.async double-buffered ===================
#define SM_LD 40
#define TILE_B (128 * SM_LD * 2)
#define BUF_B  (4 * TILE_B)
#define SMEM_TOTAL (2 * BUF_B)   // 81920 B

static __device__ __forceinline__ void cp16(uint32_t dst, const void* src) {
    asm volatile("cp.async.cg.shared.global [%0], [%1], 16;" :: "r"(dst), "l"(src));
}
static __device__ __forceinline__ void cp_commit() {
    asm volatile("cp.async.commit_group;");
}
template<int N> static __device__ __forceinline__ void cp_wait() {
    asm volatile("cp.async.wait_group %0;" :: "n"(N));
}
static __device__ __forceinline__ void cp_tile(
    uint32_t dst_tile, const __nv_bfloat16* src0, int rowbytes, int tid)
{
    const char* src = (const char*)src0;
#pragma unroll
    for (int r = 0; r < 2; ++r) {
        int c = tid + r * 256;
        int row = c >> 2, seg = c & 3;
        cp16(dst_tile + row * (SM_LD * 2) + seg * 16,
             src + (size_t)row * rowbytes + seg * 16);
    }
}
static __device__ __forceinline__ void lds_x4(uint32_t addr, uint32_t& r0, uint32_t& r1,
                                              uint32_t& r2, uint32_t& r3) {
    asm volatile("ldmatrix.sync.aligned.m8n8.x4.shared.b16 {%0,%1,%2,%3}, [%4];\n"
                 : "=r"(r0), "=r"(r1), "=r"(r2), "=r"(r3) : "r"(addr));
}
static __device__ __forceinline__ void mma_bf16(float* c, const uint32_t* a, uint32_t b0, uint32_t b1) {
    asm volatile(
        "mma.sync.aligned.m16n8k16.row.col.f32.bf16.bf16.f32 "
        "{%0,%1,%2,%3}, {%4,%5,%6,%7}, {%8,%9}, {%0,%1,%2,%3};\n"
        : "+f"(c[0]), "+f"(c[1]), "+f"(c[2]), "+f"(c[3])
        : "r"(a[0]), "r"(a[1]), "r"(a[2]), "r"(a[3]), "r"(b0), "r"(b1));
}
static __device__ __forceinline__ void mma_k16(
    float (&c)[2][8][4], uint32_t Ahi, uint32_t Alo, uint32_t Bhi, uint32_t Blo,
    int m_local, int n_local, int lane, int k16)
{
    const int aRow = (lane & 7) + ((lane >> 3) & 1) * 8;
    const int aCol = k16 + (lane >> 4) * 8;
    const int bRow = (lane & 7) + ((lane >> 4) & 1) * 8;
    const int bCol = k16 + ((lane >> 3) & 1) * 8;

    uint32_t ah[2][4], al[2][4], bh[4][4], bl[4][4];
#pragma unroll
    for (int i = 0; i < 2; ++i)
        lds_x4(Ahi + ((m_local + 16 * i + aRow) * SM_LD + aCol) * 2,
               ah[i][0], ah[i][1], ah[i][2], ah[i][3]);
#pragma unroll
    for (int jj = 0; jj < 4; ++jj)
        lds_x4(Bhi + ((n_local + 16 * jj + bRow) * SM_LD + bCol) * 2,
               bh[jj][0], bh[jj][1], bh[jj][2], bh[jj][3]);
#pragma unroll
    for (int i = 0; i < 2; ++i)
#pragma unroll
        for (int j = 0; j < 8; ++j)
            mma_bf16(c[i][j], ah[i], bh[j >> 1][(j & 1) * 2], bh[j >> 1][(j & 1) * 2 + 1]);
#pragma unroll
    for (int jj = 0; jj < 4; ++jj)
        lds_x4(Blo + ((n_local + 16 * jj + bRow) * SM_LD + bCol) * 2,
               bl[jj][0], bl[jj][1], bl[jj][2], bl[jj][3]);
#pragma unroll
    for (int i = 0; i < 2; ++i)
#pragma unroll
        for (int j = 0; j < 8; ++j)
            mma_bf16(c[i][j], ah[i], bl[j >> 1][(j & 1) * 2], bl[j >> 1][(j & 1) * 2 + 1]);
#pragma unroll
    for (int i = 0; i < 2; ++i)
        lds_x4(Alo + ((m_local + 16 * i + aRow) * SM_LD + aCol) * 2,
               al[i][0], al[i][1], al[i][2], al[i][3]);
#pragma unroll
    for (int i = 0; i < 2; ++i)
#pragma unroll
        for (int j = 0; j < 8; ++j)
            mma_bf16(c[i][j], al[i], bh[j >> 1][(j & 1) * 2], bh[j >> 1][(j & 1) * 2 + 1]);
}
static __device__ __forceinline__ void issue_chunk(
    uint32_t smb, int buf, const __nv_bfloat16* Ah, const __nv_bfloat16* Al,
    const __nv_bfloat16* Bh, const __nv_bfloat16* Bl, int ldkB, int tid)
{
    uint32_t b = smb + buf * BUF_B;
    cp_tile(b,              Ah, ldkB, tid);
    cp_tile(b + TILE_B,     Al, ldkB, tid);
    cp_tile(b + 2 * TILE_B, Bh, ldkB, tid);
    cp_tile(b + 3 * TILE_B, Bl, ldkB, tid);
    cp_commit();
}
#define GEMM_LOOP(NCH, GET_A_H, GET_A_L, GET_B_H, GET_B_L, LDKB)                 \
    issue_chunk(smb, 0, GET_A_H(0), GET_A_L(0), GET_B_H(0), GET_B_L(0), LDKB, tid); \
    for (int ch = 0; ch < (NCH); ++ch) {                                          \
        int cur = ch & 1;                                                         \
        if (ch + 1 < (NCH)) {                                                     \
            issue_chunk(smb, cur ^ 1, GET_A_H(ch + 1), GET_A_L(ch + 1),           \
                        GET_B_H(ch + 1), GET_B_L(ch + 1), LDKB, tid);             \
            cp_wait<1>();                                                         \
        } else {                                                                  \
            cp_wait<0>();                                                         \
        }                                                                         \
        __syncthreads();                                                          \
        uint32_t b = smb + cur * BUF_B;                                           \
        mma_k16(c, b, b + TILE_B, b + 2 * TILE_B, b + 3 * TILE_B,                 \
                m_local, n_local, lane, 0);                                       \
        mma_k16(c, b, b + TILE_B, b + 2 * TILE_B, b + 3 * TILE_B,                 \
                m_local, n_local, lane, 16);                                      \
        __syncthreads();                                                          \
    }

// Layer 1: h = relu( agg1 @ W1l^T + x @ W1r^T + b1 ) -> g_hh/g_hl   grid(392, 2)
__global__ void __launch_bounds__(256)
gemm1_mma_kernel(const float* __restrict__ b1) {
    extern __shared__ char sm[];
    uint32_t smb = (uint32_t)__cvta_generic_to_shared(sm);
    const int tid = threadIdx.x, lane = tid & 31, wid = tid >> 5;
    const int m_local = (wid & 3) * 32;
    const int n_local = (wid >> 2) * 64;
    const int m0 = blockIdx.x * 128;
    const int n0 = blockIdx.y * 128;

    float c[2][8][4];
#pragma unroll
    for (int i = 0; i < 2; ++i)
#pragma unroll
        for (int j = 0; j < 8; ++j)
#pragma unroll
            for (int k = 0; k < 4; ++k) c[i][j][k] = 0.f;

#define GA_H(ch) (((ch) < 4 ? g_a1h : g_xh) + (size_t)m0 * DIN + ((ch) & 3) * 32)
#define GA_L(ch) (((ch) < 4 ? g_a1l : g_xl) + (size_t)m0 * DIN + ((ch) & 3) * 32)
#define GB_H(ch) (g_w1h + (size_t)(((ch) < 4 ? 0 : 256) + n0) * DIN + ((ch) & 3) * 32)
#define GB_L(ch) (g_w1l + (size_t)(((ch) < 4 ? 0 : 256) + n0) * DIN + ((ch) & 3) * 32)
    GEMM_LOOP(8, GA_H, GA_L, GB_H, GB_L, DIN * 2)
#undef GA_H
#undef GA_L
#undef GB_H
#undef GB_L

    const int gid = lane >> 2, tig = lane & 3;
#pragma unroll
    for (int i = 0; i < 2; ++i) {
        int row = m0 + m_local + 16 * i + gid;
#pragma unroll
        for (int j = 0; j < 8; ++j) {
            int col = n0 + n_local + 8 * j + 2 * tig;
            float bb0 = b1[col], bb1 = b1[col + 1];
            if (row < N_NODES) {
                float v0 = fmaxf(c[i][j][0] + bb0, 0.f);
                float v1 = fmaxf(c[i][j][1] + bb1, 0.f);
                __nv_bfloat16 h0, l0, h1, l1;
                split2(v0, h0, l0); split2(v1, h1, l1);
                *(uint32_t*)&g_hh[(size_t)row * DH + col] = pack_bf16x2(h0, h1);
                *(uint32_t*)&g_hl[(size_t)row * DH + col] = pack_bf16x2(l0, l1);
            }
            if (row + 8 < N_NODES) {
                float v0 = fmaxf(c[i][j][2] + bb0, 0.f);
                float v1 = fmaxf(c[i][j][3] + bb1, 0.f);
                __nv_bfloat16 h0, l0, h1, l1;
                split2(v0, h0, l0); split2(v1, h1, l1);
                *(uint32_t*)&g_hh[(size_t)(row + 8) * DH + col] = pack_bf16x2(h0, h1);
                *(uint32_t*)&g_hl[(size_t)(row + 8) * DH + col] = pack_bf16x2(l0, l1);
            }
        }
    }
}

// gemm2: P = h @ [W2l;W2r]^T -> g_P (fp32)   grid(392, 1), K=256
__global__ void __launch_bounds__(256)
gemm2_mma_kernel() {
    extern __shared__ char sm[];
    uint32_t smb = (uint32_t)__cvta_generic_to_shared(sm);
    const int tid = threadIdx.x, lane = tid & 31, wid = tid >> 5;
    const int m_local = (wid & 3) * 32;
    const int n_local = (wid >> 2) * 64;
    const int m0 = blockIdx.x * 128;

    float c[2][8][4];
#pragma unroll
    for (int i = 0; i < 2; ++i)
#pragma unroll
        for (int j = 0; j < 8; ++j)
#pragma unroll
            for (int k = 0; k < 4; ++k) c[i][j][k] = 0.f;

#define HA_H(ch) (g_hh + (size_t)m0 * DH + (ch) * 32)
#define HA_L(ch) (g_hl + (size_t)m0 * DH + (ch) * 32)
#define HB_H(ch) (g_w2h + (ch) * 32)
#define HB_L(ch) (g_w2l + (ch) * 32)
    GEMM_LOOP(8, HA_H, HA_L, HB_H, HB_L, DH * 2)
#undef HA_H
#undef HA_L
#undef HB_H
#undef HB_L

    const int gid = lane >> 2, tig = lane & 3;
#pragma unroll
    for (int i = 0; i < 2; ++i) {
        int row = m0 + m_local + 16 * i + gid;
#pragma unroll
        for (int j = 0; j < 8; ++j) {
            int col = n_local + 8 * j + 2 * tig;
            if (row < N_NODES)
                *(float2*)&g_P[(size_t)row * 2 * DOUT + col] =
                    make_float2(c[i][j][0], c[i][j][1]);
            if (row + 8 < N_NODES)
                *(float2*)&g_P[(size_t)(row + 8) * 2 * DOUT + col] =
                    make_float2(c[i][j][2], c[i][j][3]);
        }
    }
}

// ---- layer-2 aggregation + combine (gather, warp per node, unroll 8) ----------
__global__ void __launch_bounds__(256)
agg2_final_kernel(const float* __restrict__ b2, float* __restrict__ out) {
    int w    = (blockIdx.x * blockDim.x + threadIdx.x) >> 5;
    int lane = threadIdx.x & 31;
    if (w >= N_NODES) return;
    int start = g_rowptr[w], end = g_rowptr[w + 1];
    const float2* Pv = (const float2*)g_P;
    float2 acc = make_float2(0.f, 0.f);
    int p = start;
    for (; p + 8 <= end; p += 8) {
        int s0 = g_col[p],     s1 = g_col[p + 1], s2 = g_col[p + 2], s3 = g_col[p + 3];
        int s4 = g_col[p + 4], s5 = g_col[p + 5], s6 = g_col[p + 6], s7 = g_col[p + 7];
        float2 v0 = Pv[(long long)s0 * 64 + lane];
        float2 v1 = Pv[(long long)s1 * 64 + lane];
        float2 v2 = Pv[(long long)s2 * 64 + lane];
        float2 v3 = Pv[(long long)s3 * 64 + lane];
        float2 v4 = Pv[(long long)s4 * 64 + lane];
        float2 v5 = Pv[(long long)s5 * 64 + lane];
        float2 v6 = Pv[(long long)s6 * 64 + lane];
        float2 v7 = Pv[(long long)s7 * 64 + lane];
        acc.x += (v0.x + v1.x) + (v2.x + v3.x) + (v4.x + v5.x) + (v6.x + v7.x);
        acc.y += (v0.y + v1.y) + (v2.y + v3.y) + (v4.y + v5.y) + (v6.y + v7.y);
    }
    for (; p + 4 <= end; p += 4) {
        int s0 = g_col[p], s1 = g_col[p + 1], s2 = g_col[p + 2], s3 = g_col[p + 3];
        float2 v0 = Pv[(long long)s0 * 64 + lane];
        float2 v1 = Pv[(long long)s1 * 64 + lane];
        float2 v2 = Pv[(long long)s2 * 64 + lane];
        float2 v3 = Pv[(long long)s3 * 64 + lane];
        acc.x += v0.x + v1.x + v2.x + v3.x;
        acc.y += v0.y + v1.y + v2.y + v3.y;
    }
    for (; p < end; ++p) {
        float2 v = Pv[(long long)g_col[p] * 64 + lane];
        acc.x += v.x; acc.y += v.y;
    }
    float inv = g_inv[w];
    float2 root = Pv[(long long)w * 64 + 32 + lane];
    float2 bias = ((const float2*)b2)[lane];
    float2 o;
    o.x = acc.x * inv + root.x + bias.x;
    o.y = acc.y * inv + root.y + bias.y;
    ((float2*)out)[(long long)w * 32 + lane] = o;
}

// ---------------- launch --------------------------------------------------------
extern "C" void kernel_launch(void* const* d_in, const int* in_sizes, int n_in,
                              void* d_out, int out_size) {
    const float* x   = (const float*)d_in[0];
    const void*  ei  = d_in[1];
    const float* W1l = (const float*)d_in[2];
    const float* W1r = (const float*)d_in[3];
    const float* b1  = (const float*)d_in[4];
    const float* W2l = (const float*)d_in[5];
    const float* W2r = (const float*)d_in[6];
    const float* b2  = (const float*)d_in[7];
    float*       out = (float*)d_out;

    cudaFuncSetAttribute(gemm1_mma_kernel,
                         cudaFuncAttributeMaxDynamicSharedMemorySize, SMEM_TOTAL);
    cudaFuncSetAttribute(gemm2_mma_kernel,
                         cudaFuncAttributeMaxDynamicSharedMemorySize, SMEM_TOTAL);

    {
        const int total = N_NODES * (DIN / 4) + 512 * DIN + 128 * DH + N_NODES;
        prep_kernel<<<(total + 255) / 256, 256>>>(x, W1l, W1r, W2l, W2r,
                                                  (const unsigned int*)ei);
    }
    count_kernel<<<(N_EDGES / 4 + 255) / 256, 256>>>(ei);
    blocksum_kernel<<<NB_SCAN, 256>>>();
    rowptr_kernel<<<NB_SCAN, 256>>>();
    fill_kernel<<<(N_EDGES / 2 + 255) / 256, 256>>>(ei);
    agg1_kernel<<<(N_NODES * 32 + 255) / 256, 256>>>(x);
    {
        dim3 grid(N_PAD / 128, 2);
        gemm1_mma_kernel<<<grid, 256, SMEM_TOTAL>>>(b1);
    }
    {
        dim3 grid(N_PAD / 128, 1);
        gemm2_mma_kernel<<<grid, 256, SMEM_TOTAL>>>();
    }
    agg2_final_kernel<<<(N_NODES * 32 + 255) / 256, 256>>>(b2, out);
}